// round 16
// baseline (speedup 1.0000x reference)
#include <cuda_runtime.h>

#define NN 80000
#define EE 1280000
#define GG 512
#define HD 64
#define NCLS 10

#define SCAN_BLKS 79   // 79 * 1024 = 80896 >= NN

// Scratch (static device globals; 16B aligned)
__device__ __align__(16) float g_h1[NN * HD];
__device__ __align__(16) float g_h2[NN * HD];
// CSR scratch
__device__ __align__(16) int g_deg[SCAN_BLKS * 1024];     // padded, zeroed
__device__ __align__(16) int g_rowstart[NN + 4];
__device__ __align__(16) int g_cursor[SCAN_BLKS * 1024];
__device__ int g_partial[SCAN_BLKS];
__device__ int g_partbase[SCAN_BLKS];
__device__ int g_csrsrc[EE];
__device__ int g_bnd[GG + 1];

// ---- packed f32x2 helpers (sm_103a FFMA2/FADD2 via PTX) --------------------
__device__ __forceinline__ unsigned long long f2pack(float lo, float hi) {
    unsigned long long r;
    asm("mov.b64 %0, {%1, %2};" : "=l"(r) : "r"(__float_as_uint(lo)), "r"(__float_as_uint(hi)));
    return r;
}
__device__ __forceinline__ void f2unpack(unsigned long long v, float& lo, float& hi) {
    unsigned int a, b;
    asm("mov.b64 {%0, %1}, %2;" : "=r"(a), "=r"(b) : "l"(v));
    lo = __uint_as_float(a);
    hi = __uint_as_float(b);
}
__device__ __forceinline__ unsigned long long f2fma(unsigned long long a,
                                                    unsigned long long b,
                                                    unsigned long long c) {
    unsigned long long d;
    asm("fma.rn.f32x2 %0, %1, %2, %3;" : "=l"(d) : "l"(a), "l"(b), "l"(c));
    return d;
}
__device__ __forceinline__ unsigned long long f2add(unsigned long long a,
                                                    unsigned long long b) {
    unsigned long long d;
    asm("add.rn.f32x2 %0, %1, %2;" : "=l"(d) : "l"(a), "l"(b));
    return d;
}

// ---------------------------------------------------------------------------
__global__ void zero_deg_kernel() {
    int i = blockIdx.x * blockDim.x + threadIdx.x;
    if (i < SCAN_BLKS * 1024) g_deg[i] = 0;
}

__global__ void hist_kernel(const int* __restrict__ ei) {
    int e = blockIdx.x * blockDim.x + threadIdx.x;
    if (e >= EE) return;
    int d = ei[EE + e];
    if ((unsigned)d < NN) atomicAdd(&g_deg[d], 1);
}

// Graph boundaries: g_bnd[g] = lower_bound(batch, g)
__global__ void bnd_kernel(const int* __restrict__ batch) {
    int g = blockIdx.x * blockDim.x + threadIdx.x;
    if (g > GG) return;
    int lo = 0, hi = NN;
    while (lo < hi) {
        int mid = (lo + hi) >> 1;
        if (batch[mid] < g) lo = mid + 1; else hi = mid;
    }
    g_bnd[g] = lo;
}

__global__ void scan1_kernel() {
    __shared__ int sred[256];
    int t = threadIdx.x;
    int4 v = ((const int4*)g_deg)[blockIdx.x * 256 + t];
    int s = v.x + v.y + v.z + v.w;
    sred[t] = s;
    __syncthreads();
    for (int off = 128; off > 0; off >>= 1) {
        if (t < off) sred[t] += sred[t + off];
        __syncthreads();
    }
    if (t == 0) g_partial[blockIdx.x] = sred[0];
}

__global__ void scan2_kernel() {
    __shared__ int sp[128];
    int t = threadIdx.x;
    sp[t] = (t < SCAN_BLKS) ? g_partial[t] : 0;
    __syncthreads();
    for (int off = 1; off < 128; off <<= 1) {
        int add = (t >= off) ? sp[t - off] : 0;
        __syncthreads();
        sp[t] += add;
        __syncthreads();
    }
    if (t < SCAN_BLKS) g_partbase[t] = sp[t] - g_partial[t];
    if (t == 0) g_rowstart[NN] = EE;
}

__global__ void scan3_kernel() {
    __shared__ int sscan[256];
    int t = threadIdx.x;
    int idx4 = blockIdx.x * 256 + t;
    int4 v = ((const int4*)g_deg)[idx4];
    int s = v.x + v.y + v.z + v.w;
    sscan[t] = s;
    __syncthreads();
    for (int off = 1; off < 256; off <<= 1) {
        int add = (t >= off) ? sscan[t - off] : 0;
        __syncthreads();
        sscan[t] += add;
        __syncthreads();
    }
    int run = g_partbase[blockIdx.x] + sscan[t] - s;
    int4 rs;
    rs.x = run;
    rs.y = run + v.x;
    rs.z = run + v.x + v.y;
    rs.w = run + v.x + v.y + v.z;
    int base = idx4 * 4;
    if (base < NN) {
        if (base + 3 < NN) ((int4*)g_rowstart)[idx4] = rs;
        else {
            if (base + 0 < NN) g_rowstart[base + 0] = rs.x;
            if (base + 1 < NN) g_rowstart[base + 1] = rs.y;
            if (base + 2 < NN) g_rowstart[base + 2] = rs.z;
            if (base + 3 < NN) g_rowstart[base + 3] = rs.w;
        }
    }
    ((int4*)g_cursor)[idx4] = rs;
}

__global__ void fill_kernel(const int* __restrict__ ei) {
    int e = blockIdx.x * blockDim.x + threadIdx.x;
    if (e >= EE) return;
    int s = ei[e];
    int d = ei[EE + e];
    if ((unsigned)s >= NN || (unsigned)d >= NN) return;
    int pos = atomicAdd(&g_cursor[d], 1);
    g_csrsrc[pos] = s;
}

// ---------------------------------------------------------------------------
// FUSED layer, 64 nodes/block, 256 threads, 48KB static smem.
// Gather is software-pipelined with packed f32x2 adds; GEMM phases use
// packed f32x2 FMA (FFMA2) -> half the FMA instruction count.
__global__ void fused_layer_kernel(int selIn, const float* __restrict__ x_arg,
                                   int selOut,
                                   const float* __restrict__ wrel,
                                   const float* __restrict__ brel,
                                   const float* __restrict__ wroot,
                                   int relu) {
    __shared__ float sW[2][64 * 64];   // [0]=Wrel^T, [1]=Wroot^T (k-major)
    __shared__ float sT[64 * 64];      // 16KB node tile

    const float* xin = (selIn == 0) ? x_arg : ((selIn == 1) ? g_h1 : g_h2);
    float* out = (selOut == 1) ? g_h1 : g_h2;

    int tid = threadIdx.x;
    int nodeBase = blockIdx.x * 64;

    // Weight loads issued early; latency overlaps gather
    for (int i = tid; i < 4096; i += 256) {
        int jj = i >> 6, k = i & 63;
        sW[0][k * 64 + jj] = wrel[i];
        sW[1][k * 64 + jj] = wroot[i];
    }

    // Phase G: 16 threads/node, 4 nodes/thread, pipelined, packed adds
    {
        int q = tid & 15;
        int ln = tid >> 4;
        const float4* s4 = (const float4*)xin;
#pragma unroll
        for (int half = 0; half < 4; half++) {
            int n = nodeBase + ln + half * 16;
            int jj = g_rowstart[n];
            int jend = g_rowstart[n + 1];
            unsigned long long aLo = 0, aHi = 0, bLo = 0, bHi = 0; // 0.0f pairs
            int nfull = (jend - jj) >> 2;
            if (nfull > 0) {
                int i0 = g_csrsrc[jj], i1 = g_csrsrc[jj + 1];
                int i2 = g_csrsrc[jj + 2], i3 = g_csrsrc[jj + 3];
                ulonglong2 v0 = *(const ulonglong2*)(s4 + i0 * 16 + q);
                ulonglong2 v1 = *(const ulonglong2*)(s4 + i1 * 16 + q);
                ulonglong2 v2 = *(const ulonglong2*)(s4 + i2 * 16 + q);
                ulonglong2 v3 = *(const ulonglong2*)(s4 + i3 * 16 + q);
                for (int b = 1; b < nfull; b++) {
                    jj += 4;
                    int k0 = g_csrsrc[jj], k1 = g_csrsrc[jj + 1];
                    int k2 = g_csrsrc[jj + 2], k3 = g_csrsrc[jj + 3];
                    ulonglong2 w0 = *(const ulonglong2*)(s4 + k0 * 16 + q);
                    ulonglong2 w1 = *(const ulonglong2*)(s4 + k1 * 16 + q);
                    ulonglong2 w2 = *(const ulonglong2*)(s4 + k2 * 16 + q);
                    ulonglong2 w3 = *(const ulonglong2*)(s4 + k3 * 16 + q);
                    aLo = f2add(aLo, f2add(v0.x, v1.x));
                    aHi = f2add(aHi, f2add(v0.y, v1.y));
                    bLo = f2add(bLo, f2add(v2.x, v3.x));
                    bHi = f2add(bHi, f2add(v2.y, v3.y));
                    v0 = w0; v1 = w1; v2 = w2; v3 = w3;
                }
                aLo = f2add(aLo, f2add(v0.x, v1.x));
                aHi = f2add(aHi, f2add(v0.y, v1.y));
                bLo = f2add(bLo, f2add(v2.x, v3.x));
                bHi = f2add(bHi, f2add(v2.y, v3.y));
                jj += 4;
            }
            for (; jj < jend; jj++) {
                int i0 = g_csrsrc[jj];
                ulonglong2 v = *(const ulonglong2*)(s4 + i0 * 16 + q);
                aLo = f2add(aLo, v.x);
                aHi = f2add(aHi, v.y);
            }
            aLo = f2add(aLo, bLo);
            aHi = f2add(aHi, bHi);
            ulonglong2 res; res.x = aLo; res.y = aHi;
            *(ulonglong2*)(&sT[(ln + half * 16) * 64 + q * 4]) = res;
        }
    }
    __syncthreads();

    int jg = tid & 15;
    int ng = tid >> 4;
    int j0 = jg * 4;
    int n0 = ng * 4;

    // Packed accumulators: [node][xy|zw]
    float4 bb = *(const float4*)(brel + j0);
    unsigned long long axy[4], azw[4];
    {
        unsigned long long bxy = f2pack(bb.x, bb.y);
        unsigned long long bzw = f2pack(bb.z, bb.w);
#pragma unroll
        for (int r = 0; r < 4; r++) { axy[r] = bxy; azw[r] = bzw; }
    }

    // Phase A: agg @ Wrel^T (packed FMA)
#pragma unroll 4
    for (int k = 0; k < 64; k++) {
        ulonglong2 w = *(const ulonglong2*)(&sW[0][k * 64 + j0]);
        float a0 = sT[(n0 + 0) * 64 + k];
        float a1 = sT[(n0 + 1) * 64 + k];
        float a2 = sT[(n0 + 2) * 64 + k];
        float a3 = sT[(n0 + 3) * 64 + k];
        unsigned long long p0 = f2pack(a0, a0);
        unsigned long long p1 = f2pack(a1, a1);
        unsigned long long p2 = f2pack(a2, a2);
        unsigned long long p3 = f2pack(a3, a3);
        axy[0] = f2fma(p0, w.x, axy[0]); azw[0] = f2fma(p0, w.y, azw[0]);
        axy[1] = f2fma(p1, w.x, axy[1]); azw[1] = f2fma(p1, w.y, azw[1]);
        axy[2] = f2fma(p2, w.x, axy[2]); azw[2] = f2fma(p2, w.y, azw[2]);
        axy[3] = f2fma(p3, w.x, axy[3]); azw[3] = f2fma(p3, w.y, azw[3]);
    }
    __syncthreads();

    // Stage x tile (64 rows, contiguous float4 copy)
    {
        const float4* src = (const float4*)(xin + nodeBase * 64);
        float4* dst = (float4*)sT;
        for (int i = tid; i < 1024; i += 256) dst[i] = src[i];
    }
    __syncthreads();

    // Phase X: x @ Wroot^T (packed FMA)
#pragma unroll 4
    for (int k = 0; k < 64; k++) {
        ulonglong2 w = *(const ulonglong2*)(&sW[1][k * 64 + j0]);
        float a0 = sT[(n0 + 0) * 64 + k];
        float a1 = sT[(n0 + 1) * 64 + k];
        float a2 = sT[(n0 + 2) * 64 + k];
        float a3 = sT[(n0 + 3) * 64 + k];
        unsigned long long p0 = f2pack(a0, a0);
        unsigned long long p1 = f2pack(a1, a1);
        unsigned long long p2 = f2pack(a2, a2);
        unsigned long long p3 = f2pack(a3, a3);
        axy[0] = f2fma(p0, w.x, axy[0]); azw[0] = f2fma(p0, w.y, azw[0]);
        axy[1] = f2fma(p1, w.x, axy[1]); azw[1] = f2fma(p1, w.y, azw[1]);
        axy[2] = f2fma(p2, w.x, axy[2]); azw[2] = f2fma(p2, w.y, azw[2]);
        axy[3] = f2fma(p3, w.x, axy[3]); azw[3] = f2fma(p3, w.y, azw[3]);
    }

#pragma unroll
    for (int r = 0; r < 4; r++) {
        float4 v;
        f2unpack(axy[r], v.x, v.y);
        f2unpack(azw[r], v.z, v.w);
        if (relu) {
            v.x = fmaxf(v.x, 0.f); v.y = fmaxf(v.y, 0.f);
            v.z = fmaxf(v.z, 0.f); v.w = fmaxf(v.w, 0.f);
        }
        *(float4*)(out + (nodeBase + n0 + r) * 64 + j0) = v;
    }
}

// ---------------------------------------------------------------------------
// Fused pool+head: one block per graph. 256 threads = 64 dims x 4 node-lanes.
__global__ void poolhead_kernel(const float* __restrict__ w_lin,
                                const float* __restrict__ b_lin,
                                float* __restrict__ out) {
    __shared__ float sred[256];
    __shared__ float sp[64];
    int g = blockIdx.x;
    int tid = threadIdx.x;
    int d = tid & 63;
    int r = tid >> 6;
    int start = g_bnd[g];
    int end = g_bnd[g + 1];

    float acc = 0.f;
    for (int n = start + r; n < end; n += 4)
        acc += g_h1[n * HD + d];
    sred[tid] = acc;
    __syncthreads();
    if (tid < 64)
        sp[tid] = sred[tid] + sred[tid + 64] + sred[tid + 128] + sred[tid + 192];
    __syncthreads();

    if (tid < NCLS) {
        float inv = 1.f / fmaxf((float)(end - start), 1.f);
        float a = 0.f;
#pragma unroll 8
        for (int k = 0; k < HD; k++)
            a += sp[k] * w_lin[tid * HD + k];
        out[g * NCLS + tid] = b_lin[tid] + a * inv;
    }
}

// ---------------------------------------------------------------------------
extern "C" void kernel_launch(void* const* d_in, const int* in_sizes, int n_in,
                              void* d_out, int out_size) {
    (void)in_sizes; (void)n_in; (void)out_size;
    const float* x = (const float*)d_in[0];
    const int* ei = (const int*)d_in[1];      // int32
    const int* batch = (const int*)d_in[2];   // int32
    const float* wr1 = (const float*)d_in[3];
    const float* br1 = (const float*)d_in[4];
    const float* wo1 = (const float*)d_in[5];
    const float* wr2 = (const float*)d_in[6];
    const float* br2 = (const float*)d_in[7];
    const float* wo2 = (const float*)d_in[8];
    const float* wr3 = (const float*)d_in[9];
    const float* br3 = (const float*)d_in[10];
    const float* wo3 = (const float*)d_in[11];
    const float* w_lin = (const float*)d_in[12];
    const float* b_lin = (const float*)d_in[13];
    float* out = (float*)d_out;

    const int eblocks = (EE + 255) / 256;
    const int fblocks = NN / 64;  // 1250

    // CSR build + graph boundaries
    zero_deg_kernel<<<(SCAN_BLKS * 1024 + 255) / 256, 256>>>();
    hist_kernel<<<eblocks, 256>>>(ei);
    bnd_kernel<<<3, 256>>>(batch);
    scan1_kernel<<<SCAN_BLKS, 256>>>();
    scan2_kernel<<<1, 128>>>();
    scan3_kernel<<<SCAN_BLKS, 256>>>();
    fill_kernel<<<eblocks, 256>>>(ei);

    // Fused gather+dense layers
    fused_layer_kernel<<<fblocks, 256>>>(0, x, 1, wr1, br1, wo1, 1);
    fused_layer_kernel<<<fblocks, 256>>>(1, x, 2, wr2, br2, wo2, 1);
    fused_layer_kernel<<<fblocks, 256>>>(2, x, 1, wr3, br3, wo3, 0);

    // Fused pool+head
    poolhead_kernel<<<GG, 256>>>(w_lin, b_lin, out);
}